// round 1
// baseline (speedup 1.0000x reference)
#include <cuda_runtime.h>

// Problem constants (fixed shapes per reference)
#define VOCAB   20000
#define TOPK    8
#define GLOVE   300
#define ROW_F   (TOPK * 2 * GLOVE)   // 4800 floats per vocab row
#define OUTC    100
#define B       32
#define L       128
#define NLAB    8
#define NPOS    (B * L)              // 4096
#define NLABTOT (NPOS * NLAB)        // 32768

// Device scratch (no allocations allowed)
__device__ unsigned int g_flags[VOCAB];
__device__ float g_lsum[VOCAB * GLOVE];   // 24 MB: per-vocab summed (and pre-scaled) 300-vector

// ---------------------------------------------------------------------------
// Kernel 1: clear usage flags
// ---------------------------------------------------------------------------
__global__ void k_clear_flags() {
    int i = blockIdx.x * blockDim.x + threadIdx.x;
    if (i < VOCAB) g_flags[i] = 0u;
}

// ---------------------------------------------------------------------------
// Kernel 2: mark used vocab entries
// ---------------------------------------------------------------------------
__global__ void k_mark_flags(const int* __restrict__ labels) {
    int i = blockIdx.x * blockDim.x + threadIdx.x;
    if (i < NLABTOT) g_flags[labels[i]] = 1u;
}

// ---------------------------------------------------------------------------
// Kernel 3: per-vocab row reduction.
// One block per vocab row. Streams 4800 contiguous floats (19200 B, 128B-aligned
// base since 19200 % 128 == 0) and produces a 300-float sum, pre-scaled by 1/128.
// Only flagged rows do work (~80% of vocab) -> ~310 MB DRAM read total.
// ---------------------------------------------------------------------------
__global__ __launch_bounds__(256) void k_rowsum(const float* __restrict__ table) {
    const int v = blockIdx.x;
    if (!g_flags[v]) return;
    const float* __restrict__ row = table + (size_t)v * ROW_F;
    const int t = threadIdx.x;
    const float scale = 1.0f / 128.0f;

    // d = t  (t in 0..255 < 300, always valid)
    {
        float s = 0.0f;
        #pragma unroll
        for (int r = 0; r < 16; ++r) s += row[r * GLOVE + t];
        g_lsum[v * GLOVE + t] = s * scale;
    }
    // d = t + 256 (remaining 44 dims)
    if (t < GLOVE - 256) {
        const int d = t + 256;
        float s = 0.0f;
        #pragma unroll
        for (int r = 0; r < 16; ++r) s += row[r * GLOVE + d];
        g_lsum[v * GLOVE + d] = s * scale;
    }
}

// ---------------------------------------------------------------------------
// Kernel 4: fused averaging-gather + GEMM + bias.
// Block = 32 positions, full 100 outputs, K=300 in 4 chunks of 75.
// 160 threads: 8 pos-groups (4 pos each) x 20 out-groups (5 outs each).
// Shared pitch 77: W rows differ by 5 -> bank step (5*77)%32 = 1 (conflict-free);
// A rows differ by 4 within a warp only across 2 distinct rows -> fine.
// ---------------------------------------------------------------------------
#define TILE_P   32
#define KC       75
#define PITCH    77
#define GTHREADS 160

__global__ __launch_bounds__(GTHREADS) void k_gemm(
    const int* __restrict__ labels,
    const float* __restrict__ w,      // [100, 300]
    const float* __restrict__ bias,   // [100]
    float* __restrict__ out)          // [4096, 100]
{
    __shared__ float A_sh[TILE_P][PITCH];
    __shared__ float W_sh[OUTC][PITCH];
    __shared__ int   s_lab[TILE_P * NLAB];   // 256 labels for this block

    const int tid   = threadIdx.x;
    const int pbase = blockIdx.x * TILE_P;
    const int ogrp  = tid % 20;   // 20 groups of 5 outputs
    const int pgrp  = tid / 20;   // 8 groups of 4 positions

    // stage labels
    for (int i = tid; i < TILE_P * NLAB; i += GTHREADS)
        s_lab[i] = labels[pbase * NLAB + i];

    float acc[4][5];
    #pragma unroll
    for (int i = 0; i < 4; ++i)
        #pragma unroll
        for (int j = 0; j < 5; ++j) acc[i][j] = 0.0f;

    __syncthreads();   // labels visible

    for (int kc = 0; kc < GLOVE; kc += KC) {
        // stage W chunk [100 x 75]
        for (int i = tid; i < OUTC * KC; i += GTHREADS) {
            int o = i / KC, kk = i % KC;
            W_sh[o][kk] = w[o * GLOVE + kc + kk];
        }
        // gather+sum A chunk [32 x 75] from L2-resident g_lsum
        for (int i = tid; i < TILE_P * KC; i += GTHREADS) {
            int pp = i / KC, kk = i % KC;
            const int* lab = &s_lab[pp * NLAB];
            float s = 0.0f;
            #pragma unroll
            for (int j = 0; j < NLAB; ++j)
                s += g_lsum[lab[j] * GLOVE + kc + kk];
            A_sh[pp][kk] = s;
        }
        __syncthreads();

        #pragma unroll 5
        for (int kk = 0; kk < KC; ++kk) {
            float a[4], wv[5];
            #pragma unroll
            for (int i = 0; i < 4; ++i) a[i] = A_sh[pgrp * 4 + i][kk];
            #pragma unroll
            for (int j = 0; j < 5; ++j) wv[j] = W_sh[ogrp * 5 + j][kk];
            #pragma unroll
            for (int i = 0; i < 4; ++i)
                #pragma unroll
                for (int j = 0; j < 5; ++j)
                    acc[i][j] += a[i] * wv[j];
        }
        __syncthreads();
    }

    // epilogue: add bias, write [p, o]
    #pragma unroll
    for (int i = 0; i < 4; ++i) {
        const int p = pbase + pgrp * 4 + i;
        #pragma unroll
        for (int j = 0; j < 5; ++j) {
            const int o = ogrp * 5 + j;
            out[p * OUTC + o] = acc[i][j] + bias[o];
        }
    }
}

// ---------------------------------------------------------------------------
extern "C" void kernel_launch(void* const* d_in, const int* in_sizes, int n_in,
                              void* d_out, int out_size) {
    const int*   labels = (const int*)  d_in[0];   // [32, 128, 8] int32
    const float* table  = (const float*)d_in[1];   // [20000, 8, 600] f32
    const float* conv_w = (const float*)d_in[2];   // [100, 300]
    const float* conv_b = (const float*)d_in[3];   // [100]
    float*       out    = (float*)d_out;           // [32, 128, 100]

    (void)in_sizes; (void)n_in; (void)out_size;

    k_clear_flags<<<(VOCAB + 255) / 256, 256>>>();
    k_mark_flags<<<(NLABTOT + 255) / 256, 256>>>(labels);
    k_rowsum<<<VOCAB, 256>>>(table);
    k_gemm<<<NPOS / TILE_P, GTHREADS>>>(labels, conv_w, conv_b, out);
}

// round 2
// speedup vs baseline: 1.1485x; 1.1485x over previous
#include <cuda_runtime.h>

// Problem constants (fixed shapes per reference)
#define VOCAB   20000
#define TOPK    8
#define GLOVE   300
#define ROW_F   (TOPK * 2 * GLOVE)   // 4800 floats per vocab row
#define OUTC    100
#define B       32
#define L       128
#define NLAB    8
#define NPOS    (B * L)              // 4096
#define NLABTOT (NPOS * NLAB)        // 32768

// Device scratch (no allocations allowed)
__device__ unsigned int g_flags[VOCAB];
__device__ float g_lsum[VOCAB * GLOVE];   // 24 MB: per-vocab summed+prescaled 300-vec
__device__ float g_A[NPOS * GLOVE];       // 4.9 MB: per-position averaged 300-vec

// ---------------------------------------------------------------------------
// Kernel 1: clear usage flags
// ---------------------------------------------------------------------------
__global__ void k_clear_flags() {
    int i = blockIdx.x * blockDim.x + threadIdx.x;
    if (i < VOCAB) g_flags[i] = 0u;
}

// ---------------------------------------------------------------------------
// Kernel 2: mark used vocab entries
// ---------------------------------------------------------------------------
__global__ void k_mark_flags(const int* __restrict__ labels) {
    int i = blockIdx.x * blockDim.x + threadIdx.x;
    if (i < NLABTOT) g_flags[labels[i]] = 1u;
}

// ---------------------------------------------------------------------------
// Kernel 3: per-vocab row reduction (DRAM-streaming bound, ~310 MB total).
// One block per vocab row; only flagged rows do work.
// ---------------------------------------------------------------------------
__global__ __launch_bounds__(256) void k_rowsum(const float* __restrict__ table) {
    const int v = blockIdx.x;
    if (!g_flags[v]) return;
    const float* __restrict__ row = table + (size_t)v * ROW_F;
    const int t = threadIdx.x;
    const float scale = 1.0f / 128.0f;

    {
        float s = 0.0f;
        #pragma unroll
        for (int r = 0; r < 16; ++r) s += row[r * GLOVE + t];
        g_lsum[v * GLOVE + t] = s * scale;
    }
    if (t < GLOVE - 256) {
        const int d = t + 256;
        float s = 0.0f;
        #pragma unroll
        for (int r = 0; r < 16; ++r) s += row[r * GLOVE + d];
        g_lsum[v * GLOVE + d] = s * scale;
    }
}

// ---------------------------------------------------------------------------
// Kernel 4: averaging gather. One float4 per thread: 4096*75 = 307200 threads.
// 75 consecutive threads share one position -> label loads are warp-broadcast.
// 8 independent float4 L2 loads per thread (MLP=8), huge TLP.
// ---------------------------------------------------------------------------
#define GATHER_THREADS 256
#define GATHER_TOTAL   (NPOS * (GLOVE / 4))   // 307200

__global__ __launch_bounds__(GATHER_THREADS) void k_gather(const int* __restrict__ labels) {
    const int i = blockIdx.x * GATHER_THREADS + threadIdx.x;
    if (i >= GATHER_TOTAL) return;
    const int p  = i / (GLOVE / 4);
    const int k  = (i % (GLOVE / 4)) * 4;

    const int* __restrict__ lab = labels + p * NLAB;
    int l[NLAB];
    #pragma unroll
    for (int j = 0; j < NLAB; ++j) l[j] = lab[j];

    float4 s = make_float4(0.f, 0.f, 0.f, 0.f);
    #pragma unroll
    for (int j = 0; j < NLAB; ++j) {
        const float4 v = *reinterpret_cast<const float4*>(&g_lsum[l[j] * GLOVE + k]);
        s.x += v.x; s.y += v.y; s.z += v.z; s.w += v.w;
    }
    *reinterpret_cast<float4*>(&g_A[p * GLOVE + k]) = s;
}

// ---------------------------------------------------------------------------
// Kernel 5: GEMM  out[4096,100] = A[4096,300] * W^T + bias.
// Block tile: 16 pos x 100 outs, 200 threads (8 pos-groups x 25 out-groups),
// thread tile 2 pos x 4 outs with out-stride 25 (conflict-free W_sh reads).
// K chunked by 75. W_sh pitch 101 (odd*?  101%32=5, odd -> conflict-free STS),
// A_sh pitch 77 (8 distinct broadcast rows per LDS, conflict-free).
// ---------------------------------------------------------------------------
#define GP       16     // positions per block
#define GT       200    // threads per block
#define KC2      75
#define APITCH   77
#define WPITCH   101

__global__ __launch_bounds__(GT) void k_gemm2(
    const float* __restrict__ w,      // [100, 300]
    const float* __restrict__ bias,   // [100]
    float* __restrict__ out)          // [4096, 100]
{
    __shared__ float A_sh[GP][APITCH];
    __shared__ float W_sh[KC2][WPITCH];   // transposed: [k][o]

    const int tid   = threadIdx.x;
    const int pbase = blockIdx.x * GP;
    const int pgrp  = tid / 25;    // 0..7
    const int ogrp  = tid % 25;    // 0..24; outs = ogrp + 25*j

    float acc[2][4];
    #pragma unroll
    for (int i = 0; i < 2; ++i)
        #pragma unroll
        for (int j = 0; j < 4; ++j) acc[i][j] = 0.0f;

    for (int kc = 0; kc < GLOVE; kc += KC2) {
        // stage W chunk transposed: global coalesced over kk, smem pitch odd
        for (int i = tid; i < OUTC * KC2; i += GT) {
            const int o  = i / KC2;
            const int kk = i % KC2;
            W_sh[kk][o] = w[o * GLOVE + kc + kk];
        }
        // stage A chunk (from L2-resident g_A), coalesced
        for (int i = tid; i < GP * KC2; i += GT) {
            const int pp = i / KC2;
            const int kk = i % KC2;
            A_sh[pp][kk] = g_A[(pbase + pp) * GLOVE + kc + kk];
        }
        __syncthreads();

        #pragma unroll 5
        for (int kk = 0; kk < KC2; ++kk) {
            const float a0 = A_sh[pgrp * 2 + 0][kk];
            const float a1 = A_sh[pgrp * 2 + 1][kk];
            float wv[4];
            #pragma unroll
            for (int j = 0; j < 4; ++j) wv[j] = W_sh[kk][ogrp + 25 * j];
            #pragma unroll
            for (int j = 0; j < 4; ++j) {
                acc[0][j] += a0 * wv[j];
                acc[1][j] += a1 * wv[j];
            }
        }
        __syncthreads();
    }

    // epilogue
    #pragma unroll
    for (int i = 0; i < 2; ++i) {
        const int p = pbase + pgrp * 2 + i;
        #pragma unroll
        for (int j = 0; j < 4; ++j) {
            const int o = ogrp + 25 * j;
            out[p * OUTC + o] = acc[i][j] + bias[o];
        }
    }
}

// ---------------------------------------------------------------------------
extern "C" void kernel_launch(void* const* d_in, const int* in_sizes, int n_in,
                              void* d_out, int out_size) {
    const int*   labels = (const int*)  d_in[0];   // [32, 128, 8] int32
    const float* table  = (const float*)d_in[1];   // [20000, 8, 600] f32
    const float* conv_w = (const float*)d_in[2];   // [100, 300]
    const float* conv_b = (const float*)d_in[3];   // [100]
    float*       out    = (float*)d_out;           // [32, 128, 100]

    (void)in_sizes; (void)n_in; (void)out_size;

    k_clear_flags<<<(VOCAB + 255) / 256, 256>>>();
    k_mark_flags<<<(NLABTOT + 255) / 256, 256>>>(labels);
    k_rowsum<<<VOCAB, 256>>>(table);
    k_gather<<<(GATHER_TOTAL + GATHER_THREADS - 1) / GATHER_THREADS, GATHER_THREADS>>>(labels);
    k_gemm2<<<NPOS / GP, GT>>>(conv_w, conv_b, out);
}